// round 4
// baseline (speedup 1.0000x reference)
#include <cuda_runtime.h>
#include <cstdint>
#include <math.h>
#include <math_constants.h>

#define TILE 256
#define TILE_F (TILE * 9)          // 2304 floats
#define TILE_BYTES (TILE_F * 4)    // 9216 bytes
#define STAGES 4
#define MAXGRID 2048

// per-block partials: [block][0..4] = chordal, angular, ortho, l2, fallback
__device__ float g_part[MAXGRID * 5];

// ---------------- PTX helpers ----------------
__device__ __forceinline__ uint32_t s2u(const void* p) {
    return (uint32_t)__cvta_generic_to_shared(p);
}
__device__ __forceinline__ void mbar_init(uint32_t mbar, uint32_t count) {
    asm volatile("mbarrier.init.shared.b64 [%0], %1;" :: "r"(mbar), "r"(count) : "memory");
}
__device__ __forceinline__ void mbar_expect_tx(uint32_t mbar, uint32_t bytes) {
    asm volatile("mbarrier.arrive.expect_tx.shared.b64 _, [%0], %1;"
                 :: "r"(mbar), "r"(bytes) : "memory");
}
__device__ __forceinline__ void bulk_g2s(uint32_t dst, const void* src, uint32_t bytes, uint32_t mbar) {
    asm volatile("cp.async.bulk.shared::cta.global.mbarrier::complete_tx::bytes [%0], [%1], %2, [%3];"
                 :: "r"(dst), "l"(src), "r"(bytes), "r"(mbar) : "memory");
}
__device__ __forceinline__ void mbar_wait(uint32_t mbar, uint32_t parity) {
    uint32_t done;
    asm volatile(
        "{\n\t.reg .pred p;\n\t"
        "mbarrier.try_wait.parity.acquire.cta.shared::cta.b64 p, [%1], %2;\n\t"
        "selp.b32 %0, 1, 0, p;\n\t}"
        : "=r"(done) : "r"(mbar), "r"(parity) : "memory");
    while (!done) {
        asm volatile(
            "{\n\t.reg .pred p;\n\t"
            "mbarrier.try_wait.parity.acquire.cta.shared::cta.b64 p, [%1], %2, 0x989680;\n\t"
            "selp.b32 %0, 1, 0, p;\n\t}"
            : "=r"(done) : "r"(mbar), "r"(parity) : "memory");
    }
}

// ---------------- math ----------------
__device__ __forceinline__ float clip10(float x) {
    return fminf(fmaxf(x, -10.0f), 10.0f);
}

// v: 9 clipped floats row-major in registers. Columns a1=(v0,v3,v6) etc.
__device__ __forceinline__ void gs3x3(const float v[9], float e[9]) {
    float a1x = v[0], a1y = v[3], a1z = v[6];
    float a2x = v[1], a2y = v[4], a2z = v[7];
    float a3x = v[2], a3y = v[5], a3z = v[8];

    float n1 = fmaf(a1x, a1x, fmaf(a1y, a1y, a1z * a1z));
    float i1 = rsqrtf(fmaxf(n1, 1e-24f));
    float e1x = a1x * i1, e1y = a1y * i1, e1z = a1z * i1;

    float d12 = fmaf(e1x, a2x, fmaf(e1y, a2y, e1z * a2z));
    float u2x = fmaf(-d12, e1x, a2x);
    float u2y = fmaf(-d12, e1y, a2y);
    float u2z = fmaf(-d12, e1z, a2z);
    float n2 = fmaf(u2x, u2x, fmaf(u2y, u2y, u2z * u2z));
    float i2 = rsqrtf(fmaxf(n2, 1e-24f));
    float e2x = u2x * i2, e2y = u2y * i2, e2z = u2z * i2;

    float d13 = fmaf(e1x, a3x, fmaf(e1y, a3y, e1z * a3z));
    float d23 = fmaf(e2x, a3x, fmaf(e2y, a3y, e2z * a3z));
    float u3x = a3x - fmaf(d13, e1x, d23 * e2x);
    float u3y = a3y - fmaf(d13, e1y, d23 * e2y);
    float u3z = a3z - fmaf(d13, e1z, d23 * e2z);
    float n3 = fmaf(u3x, u3x, fmaf(u3y, u3y, u3z * u3z));
    float i3 = rsqrtf(fmaxf(n3, 1e-24f));
    float e3x = u3x * i3, e3y = u3y * i3, e3z = u3z * i3;

    float cx = fmaf(e2y, e3z, -e2z * e3y);
    float cy = fmaf(e2z, e3x, -e2x * e3z);
    float cz = fmaf(e2x, e3y, -e2y * e3x);
    float det = fmaf(e1x, cx, fmaf(e1y, cy, e1z * cz));
    if (det < 0.0f) { e3x = -e3x; e3y = -e3y; e3z = -e3z; }

    e[0] = e1x; e[1] = e1y; e[2] = e1z;
    e[3] = e2x; e[4] = e2y; e[5] = e2z;
    e[6] = e3x; e[7] = e3y; e[8] = e3z;
}

__device__ __forceinline__ void row_compute(const float* __restrict__ mp,
                                            const float* __restrict__ mt,
                                            float& ch, float& ang, float& ort,
                                            float& l2, float& fb) {
    float pv[9], tv[9];
    #pragma unroll
    for (int k = 0; k < 9; k++) {
        float praw = mp[k];
        float traw = mt[k];
        float p = clip10(praw);
        pv[k] = p;
        tv[k] = clip10(traw);
        l2 = fmaf(p, p, l2);
        float d = p - traw;     // fallback: clipped pred vs raw target
        fb = fmaf(d, d, fb);
    }
    // ortho from clipped pred columns
    {
        float c11 = fmaf(pv[0], pv[0], fmaf(pv[3], pv[3], pv[6] * pv[6]));
        float c22 = fmaf(pv[1], pv[1], fmaf(pv[4], pv[4], pv[7] * pv[7]));
        float c33 = fmaf(pv[2], pv[2], fmaf(pv[5], pv[5], pv[8] * pv[8]));
        float c12 = fmaf(pv[0], pv[1], fmaf(pv[3], pv[4], pv[6] * pv[7]));
        float c13 = fmaf(pv[0], pv[2], fmaf(pv[3], pv[5], pv[6] * pv[8]));
        float c23 = fmaf(pv[1], pv[2], fmaf(pv[4], pv[5], pv[7] * pv[8]));
        float d11 = c11 - 1.0f, d22 = c22 - 1.0f, d33 = c33 - 1.0f;
        ort += d11 * d11 + d22 * d22 + d33 * d33
             + 2.0f * (c12 * c12 + c13 * c13 + c23 * c23);
    }

    float eT[9], eP[9];
    gs3x3(tv, eT);
    gs3x3(pv, eP);

    float tr = 0.0f;
    #pragma unroll
    for (int k = 0; k < 9; k++) {
        float d = eP[k] - eT[k];
        ch = fmaf(d, d, ch);
        tr = fmaf(eP[k], eT[k], tr);
    }

    tr = fminf(fmaxf(tr, -3.0f + 1e-6f), 3.0f - 1e-6f);
    float cosang = fminf(fmaxf((tr - 1.0f) * 0.5f, -1.0f + 1e-7f), 1.0f - 1e-7f);
    float a = acosf(cosang) * (180.0f / CUDART_PI_F);
    ang += (a != a) ? 180.0f : a;
}

__global__ __launch_bounds__(TILE)
void rot_loss_pipe(const float* __restrict__ pred,
                   const float* __restrict__ tgt,
                   int NT, int B) {
    __shared__ __align__(16) float sP[STAGES][TILE_F];
    __shared__ __align__(16) float sT[STAGES][TILE_F];
    __shared__ __align__(8) unsigned long long mbars[STAGES];
    __shared__ float red[8][5];

    const int tid = threadIdx.x;
    const int grid = gridDim.x;

    uint32_t mb[STAGES], pb[STAGES], tb[STAGES];
    #pragma unroll
    for (int s = 0; s < STAGES; s++) {
        mb[s] = s2u(&mbars[s]);
        pb[s] = s2u(&sP[s][0]);
        tb[s] = s2u(&sT[s][0]);
    }

    if (tid == 0) {
        #pragma unroll
        for (int s = 0; s < STAGES; s++) mbar_init(mb[s], 1);
        asm volatile("fence.proxy.async.shared::cta;" ::: "memory");
    }
    __syncthreads();

    // Prologue: fill ALL STAGES stages (issue distance = STAGES).
    if (tid == 0) {
        #pragma unroll
        for (int k = 0; k < STAGES; k++) {
            int t = blockIdx.x + k * grid;
            if (t < NT) {
                mbar_expect_tx(mb[k], 2 * TILE_BYTES);
                bulk_g2s(pb[k], pred + (long long)t * TILE_F, TILE_BYTES, mb[k]);
                bulk_g2s(tb[k], tgt  + (long long)t * TILE_F, TILE_BYTES, mb[k]);
            }
        }
    }

    float ch = 0.0f, ang = 0.0f, ort = 0.0f, l2 = 0.0f, fb = 0.0f;
    int cs = 0, cph = 0;

    for (int t = blockIdx.x; t < NT; t += grid) {
        mbar_wait(mb[cs], cph);

        row_compute(&sP[cs][tid * 9], &sT[cs][tid * 9], ch, ang, ort, l2, fb);

        __syncthreads();  // everyone done reading stage cs

        // Reissue into the just-consumed stage, STAGES tiles ahead.
        int nt = t + STAGES * grid;
        if (tid == 0 && nt < NT) {
            mbar_expect_tx(mb[cs], 2 * TILE_BYTES);
            bulk_g2s(pb[cs], pred + (long long)nt * TILE_F, TILE_BYTES, mb[cs]);
            bulk_g2s(tb[cs], tgt  + (long long)nt * TILE_F, TILE_BYTES, mb[cs]);
        }
        if (++cs == STAGES) { cs = 0; cph ^= 1; }
    }

    // Remainder rows (B not a multiple of TILE): block 0, direct global path.
    if (blockIdx.x == 0) {
        int r = NT * TILE + tid;
        if (r < B) {
            float mp[9], mt[9];
            #pragma unroll
            for (int k = 0; k < 9; k++) {
                mp[k] = pred[(long long)r * 9 + k];
                mt[k] = tgt [(long long)r * 9 + k];
            }
            row_compute(mp, mt, ch, ang, ort, l2, fb);
        }
    }

    // ---- block reduction -> per-block partial slots (no atomics) ----
    #pragma unroll
    for (int off = 16; off > 0; off >>= 1) {
        ch  += __shfl_down_sync(0xFFFFFFFFu, ch,  off);
        ang += __shfl_down_sync(0xFFFFFFFFu, ang, off);
        ort += __shfl_down_sync(0xFFFFFFFFu, ort, off);
        l2  += __shfl_down_sync(0xFFFFFFFFu, l2,  off);
        fb  += __shfl_down_sync(0xFFFFFFFFu, fb,  off);
    }
    const int wid = tid >> 5;
    const int lid = tid & 31;
    if (lid == 0) {
        red[wid][0] = ch; red[wid][1] = ang; red[wid][2] = ort;
        red[wid][3] = l2; red[wid][4] = fb;
    }
    __syncthreads();
    if (wid == 0 && lid < 8) {
        float v0 = red[lid][0], v1 = red[lid][1], v2 = red[lid][2];
        float v3 = red[lid][3], v4 = red[lid][4];
        #pragma unroll
        for (int off = 4; off > 0; off >>= 1) {
            v0 += __shfl_down_sync(0x000000FFu, v0, off);
            v1 += __shfl_down_sync(0x000000FFu, v1, off);
            v2 += __shfl_down_sync(0x000000FFu, v2, off);
            v3 += __shfl_down_sync(0x000000FFu, v3, off);
            v4 += __shfl_down_sync(0x000000FFu, v4, off);
        }
        if (lid == 0) {
            float* slot = &g_part[blockIdx.x * 5];
            slot[0] = v0; slot[1] = v1; slot[2] = v2; slot[3] = v3; slot[4] = v4;
        }
    }
}

__global__ __launch_bounds__(256)
void finalize_kernel(float* out, int nblocks, double invB, double invB9) {
    __shared__ double red[8][5];
    const int tid = threadIdx.x;
    double a0 = 0, a1 = 0, a2 = 0, a3 = 0, a4 = 0;
    for (int i = tid; i < nblocks; i += 256) {
        const float* slot = &g_part[i * 5];
        a0 += (double)slot[0]; a1 += (double)slot[1]; a2 += (double)slot[2];
        a3 += (double)slot[3]; a4 += (double)slot[4];
    }
    #pragma unroll
    for (int off = 16; off > 0; off >>= 1) {
        a0 += __shfl_down_sync(0xFFFFFFFFu, a0, off);
        a1 += __shfl_down_sync(0xFFFFFFFFu, a1, off);
        a2 += __shfl_down_sync(0xFFFFFFFFu, a2, off);
        a3 += __shfl_down_sync(0xFFFFFFFFu, a3, off);
        a4 += __shfl_down_sync(0xFFFFFFFFu, a4, off);
    }
    const int wid = tid >> 5, lid = tid & 31;
    if (lid == 0) {
        red[wid][0] = a0; red[wid][1] = a1; red[wid][2] = a2;
        red[wid][3] = a3; red[wid][4] = a4;
    }
    __syncthreads();
    if (tid == 0) {
        double s0 = 0, s1 = 0, s2 = 0, s3 = 0, s4 = 0;
        #pragma unroll
        for (int w = 0; w < 8; w++) {
            s0 += red[w][0]; s1 += red[w][1]; s2 += red[w][2];
            s3 += red[w][3]; s4 += red[w][4];
        }
        double chordal  = s0 * invB;
        double angular  = s1 * invB;
        double ortho    = s2 * invB;
        double l2       = s3 * invB9;
        double fallback = s4 * invB9;
        double total = chordal + 0.1 * angular + 0.01 * ortho + 1e-4 * l2;
        float tf = (float)total;
        out[0] = (tf != tf) ? (float)fallback : tf;
    }
}

extern "C" void kernel_launch(void* const* d_in, const int* in_sizes, int n_in,
                              void* d_out, int out_size) {
    const float* pred = (const float*)d_in[0];
    const float* tgt  = (const float*)d_in[1];
    float* out = (float*)d_out;

    const int n = in_sizes[0];
    const int B = n / 9;
    const int NT = B / TILE;                        // full tiles
    int grid = NT < 1024 ? (NT > 0 ? NT : 1) : 1024;

    rot_loss_pipe<<<grid, TILE>>>(pred, tgt, NT, B);
    finalize_kernel<<<1, 256>>>(out, grid, 1.0 / (double)B, 1.0 / ((double)B * 9.0));
}

// round 5
// speedup vs baseline: 1.2272x; 1.2272x over previous
#include <cuda_runtime.h>
#include <cstdint>
#include <math.h>
#include <math_constants.h>

#define TILE 256            // rows per tile
#define TILE_F (TILE * 9)   // 2304 floats
#define TILE_BYTES (TILE_F * 4)
#define STAGES 3
#define NTHREADS 128        // each thread handles 2 rows
#define MAXGRID 2048

// per-block partials: [block][0..4] = chordal, angular, ortho, l2, fallback
__device__ float g_part[MAXGRID * 5];
__device__ unsigned int g_count;   // zero-init; last block resets to 0

// ---------------- PTX helpers ----------------
__device__ __forceinline__ uint32_t s2u(const void* p) {
    return (uint32_t)__cvta_generic_to_shared(p);
}
__device__ __forceinline__ void mbar_init(uint32_t mbar, uint32_t count) {
    asm volatile("mbarrier.init.shared.b64 [%0], %1;" :: "r"(mbar), "r"(count) : "memory");
}
__device__ __forceinline__ void mbar_expect_tx(uint32_t mbar, uint32_t bytes) {
    asm volatile("mbarrier.arrive.expect_tx.shared.b64 _, [%0], %1;"
                 :: "r"(mbar), "r"(bytes) : "memory");
}
__device__ __forceinline__ void bulk_g2s(uint32_t dst, const void* src, uint32_t bytes, uint32_t mbar) {
    asm volatile("cp.async.bulk.shared::cta.global.mbarrier::complete_tx::bytes [%0], [%1], %2, [%3];"
                 :: "r"(dst), "l"(src), "r"(bytes), "r"(mbar) : "memory");
}
__device__ __forceinline__ void mbar_wait(uint32_t mbar, uint32_t parity) {
    uint32_t done;
    asm volatile(
        "{\n\t.reg .pred p;\n\t"
        "mbarrier.try_wait.parity.acquire.cta.shared::cta.b64 p, [%1], %2;\n\t"
        "selp.b32 %0, 1, 0, p;\n\t}"
        : "=r"(done) : "r"(mbar), "r"(parity) : "memory");
    while (!done) {
        asm volatile(
            "{\n\t.reg .pred p;\n\t"
            "mbarrier.try_wait.parity.acquire.cta.shared::cta.b64 p, [%1], %2, 0x989680;\n\t"
            "selp.b32 %0, 1, 0, p;\n\t}"
            : "=r"(done) : "r"(mbar), "r"(parity) : "memory");
    }
}

// ---------------- packed f32x2 helpers ----------------
typedef unsigned long long f2;
__device__ __forceinline__ f2 f2pack(float lo, float hi) {
    f2 r; asm("mov.b64 %0, {%1, %2};" : "=l"(r) : "f"(lo), "f"(hi)); return r;
}
__device__ __forceinline__ void f2unpack(f2 v, float& lo, float& hi) {
    asm("mov.b64 {%0, %1}, %2;" : "=f"(lo), "=f"(hi) : "l"(v));
}
__device__ __forceinline__ f2 f2fma(f2 a, f2 b, f2 c) {
    f2 d; asm("fma.rn.f32x2 %0, %1, %2, %3;" : "=l"(d) : "l"(a), "l"(b), "l"(c)); return d;
}
__device__ __forceinline__ f2 f2mul(f2 a, f2 b) {
    f2 d; asm("mul.rn.f32x2 %0, %1, %2;" : "=l"(d) : "l"(a), "l"(b)); return d;
}
__device__ __forceinline__ f2 f2add(f2 a, f2 b) {
    f2 d; asm("add.rn.f32x2 %0, %1, %2;" : "=l"(d) : "l"(a), "l"(b)); return d;
}
#define KNEG1 0xBF800000BF800000ULL   // packed (-1.0f, -1.0f)

__device__ __forceinline__ f2 f2rsqrt_guard(f2 n) {
    float lo, hi; f2unpack(n, lo, hi);
    lo = rsqrtf(fmaxf(lo, 1e-24f));
    hi = rsqrtf(fmaxf(hi, 1e-24f));
    return f2pack(lo, hi);
}

// ---------------- math ----------------
__device__ __forceinline__ float clip10(float x) {
    return fminf(fmaxf(x, -10.0f), 10.0f);
}

// acos in degrees, |err| < 0.004 deg, input already clamped to |c| <= 1-1e-7
__device__ __forceinline__ float acos_deg(float c) {
    float ax = fabsf(c);
    float t = 1.0f - ax;                 // >= 1e-7
    float s = t * rsqrtf(t);             // sqrt(1-ax)
    float p = fmaf(fmaf(fmaf(-0.0187293f, ax, 0.0742610f), ax, -0.2121144f), ax, 1.5707288f);
    float r = s * p;                     // acos(|c|) rad
    r = (c >= 0.0f) ? r : (CUDART_PI_F - r);
    return r * (180.0f / CUDART_PI_F);
}

// angular contribution from raw trace
__device__ __forceinline__ float angle_from_trace(float tr) {
    tr = fminf(fmaxf(tr, -3.0f + 1e-6f), 3.0f - 1e-6f);
    float c = fminf(fmaxf((tr - 1.0f) * 0.5f, -1.0f + 1e-7f), 1.0f - 1e-7f);
    return acos_deg(c);
}

// packed Gram-Schmidt: v[9] row-major 3x3 (two matrices in lo/hi halves),
// outputs e1(0..2), e2(3..5), e3(6..8) det-corrected.
__device__ __forceinline__ void gs3x3_p(const f2 v[9], f2 e[9]) {
    f2 n1 = f2fma(v[0], v[0], f2fma(v[3], v[3], f2mul(v[6], v[6])));
    f2 i1 = f2rsqrt_guard(n1);
    f2 e1x = f2mul(v[0], i1), e1y = f2mul(v[3], i1), e1z = f2mul(v[6], i1);

    f2 d12 = f2fma(e1x, v[1], f2fma(e1y, v[4], f2mul(e1z, v[7])));
    f2 nd12 = f2mul(d12, KNEG1);
    f2 u2x = f2fma(nd12, e1x, v[1]);
    f2 u2y = f2fma(nd12, e1y, v[4]);
    f2 u2z = f2fma(nd12, e1z, v[7]);
    f2 n2 = f2fma(u2x, u2x, f2fma(u2y, u2y, f2mul(u2z, u2z)));
    f2 i2 = f2rsqrt_guard(n2);
    f2 e2x = f2mul(u2x, i2), e2y = f2mul(u2y, i2), e2z = f2mul(u2z, i2);

    f2 d13 = f2fma(e1x, v[2], f2fma(e1y, v[5], f2mul(e1z, v[8])));
    f2 d23 = f2fma(e2x, v[2], f2fma(e2y, v[5], f2mul(e2z, v[8])));
    f2 nd13 = f2mul(d13, KNEG1), nd23 = f2mul(d23, KNEG1);
    f2 u3x = f2fma(nd13, e1x, f2fma(nd23, e2x, v[2]));
    f2 u3y = f2fma(nd13, e1y, f2fma(nd23, e2y, v[5]));
    f2 u3z = f2fma(nd13, e1z, f2fma(nd23, e2z, v[8]));
    f2 n3 = f2fma(u3x, u3x, f2fma(u3y, u3y, f2mul(u3z, u3z)));
    f2 i3 = f2rsqrt_guard(n3);
    f2 e3x = f2mul(u3x, i3), e3y = f2mul(u3y, i3), e3z = f2mul(u3z, i3);

    // det = e1 . (e2 x e3)
    f2 cx = f2fma(f2mul(e2z, e3y), KNEG1, f2mul(e2y, e3z));
    f2 cy = f2fma(f2mul(e2x, e3z), KNEG1, f2mul(e2z, e3x));
    f2 cz = f2fma(f2mul(e2y, e3x), KNEG1, f2mul(e2x, e3y));
    f2 det = f2fma(e1x, cx, f2fma(e1y, cy, f2mul(e1z, cz)));
    float dl, dh; f2unpack(det, dl, dh);
    f2 sgn = f2pack(dl < 0.0f ? -1.0f : 1.0f, dh < 0.0f ? -1.0f : 1.0f);

    e[0] = e1x; e[1] = e1y; e[2] = e1z;
    e[3] = e2x; e[4] = e2y; e[5] = e2z;
    e[6] = f2mul(e3x, sgn); e[7] = f2mul(e3y, sgn); e[8] = f2mul(e3z, sgn);
}

// ---------------- scalar fallback (remainder rows only) ----------------
__device__ __forceinline__ void gs3x3_s(const float v[9], float e[9]) {
    float n1 = fmaf(v[0], v[0], fmaf(v[3], v[3], v[6] * v[6]));
    float i1 = rsqrtf(fmaxf(n1, 1e-24f));
    float e1x = v[0] * i1, e1y = v[3] * i1, e1z = v[6] * i1;
    float d12 = fmaf(e1x, v[1], fmaf(e1y, v[4], e1z * v[7]));
    float u2x = fmaf(-d12, e1x, v[1]), u2y = fmaf(-d12, e1y, v[4]), u2z = fmaf(-d12, e1z, v[7]);
    float n2 = fmaf(u2x, u2x, fmaf(u2y, u2y, u2z * u2z));
    float i2 = rsqrtf(fmaxf(n2, 1e-24f));
    float e2x = u2x * i2, e2y = u2y * i2, e2z = u2z * i2;
    float d13 = fmaf(e1x, v[2], fmaf(e1y, v[5], e1z * v[8]));
    float d23 = fmaf(e2x, v[2], fmaf(e2y, v[5], e2z * v[8]));
    float u3x = v[2] - fmaf(d13, e1x, d23 * e2x);
    float u3y = v[5] - fmaf(d13, e1y, d23 * e2y);
    float u3z = v[8] - fmaf(d13, e1z, d23 * e2z);
    float n3 = fmaf(u3x, u3x, fmaf(u3y, u3y, u3z * u3z));
    float i3 = rsqrtf(fmaxf(n3, 1e-24f));
    float e3x = u3x * i3, e3y = u3y * i3, e3z = u3z * i3;
    float cx = fmaf(e2y, e3z, -e2z * e3y);
    float cy = fmaf(e2z, e3x, -e2x * e3z);
    float cz = fmaf(e2x, e3y, -e2y * e3x);
    float det = fmaf(e1x, cx, fmaf(e1y, cy, e1z * cz));
    if (det < 0.0f) { e3x = -e3x; e3y = -e3y; e3z = -e3z; }
    e[0] = e1x; e[1] = e1y; e[2] = e1z;
    e[3] = e2x; e[4] = e2y; e[5] = e2z;
    e[6] = e3x; e[7] = e3y; e[8] = e3z;
}

__global__ __launch_bounds__(NTHREADS, 4)
void rot_loss_pipe(const float* __restrict__ pred,
                   const float* __restrict__ tgt,
                   int NT, int B, int grid,
                   double invB, double invB9,
                   float* __restrict__ out) {
    __shared__ __align__(16) float sP[STAGES][TILE_F];
    __shared__ __align__(16) float sT[STAGES][TILE_F];
    __shared__ __align__(8) unsigned long long mbars[STAGES];
    __shared__ float red[4][5];
    __shared__ int s_islast;

    const int tid = threadIdx.x;

    uint32_t mb[STAGES], pb[STAGES], tb[STAGES];
    #pragma unroll
    for (int s = 0; s < STAGES; s++) {
        mb[s] = s2u(&mbars[s]);
        pb[s] = s2u(&sP[s][0]);
        tb[s] = s2u(&sT[s][0]);
    }

    if (tid == 0) {
        #pragma unroll
        for (int s = 0; s < STAGES; s++) mbar_init(mb[s], 1);
        asm volatile("fence.proxy.async.shared::cta;" ::: "memory");
    }
    __syncthreads();

    // Prologue: fill ALL stages (issue distance = STAGES).
    if (tid == 0) {
        #pragma unroll
        for (int k = 0; k < STAGES; k++) {
            int t = blockIdx.x + k * grid;
            if (t < NT) {
                mbar_expect_tx(mb[k], 2 * TILE_BYTES);
                bulk_g2s(pb[k], pred + (long long)t * TILE_F, TILE_BYTES, mb[k]);
                bulk_g2s(tb[k], tgt  + (long long)t * TILE_F, TILE_BYTES, mb[k]);
            }
        }
    }

    // packed accumulators
    f2 l2a = 0, fba = 0, orda = 0, oroa = 0, tra = 0;
    float ang = 0.0f, tr_s = 0.0f, l2_s = 0.0f, fb_s = 0.0f, or_s = 0.0f;
    int cnt = 0;
    int cs = 0, cph = 0;

    for (int t = blockIdx.x; t < NT; t += grid, cnt += 2) {
        mbar_wait(mb[cs], cph);

        const float* rpA = &sP[cs][tid * 9];
        const float* rpB = &sP[cs][(tid + NTHREADS) * 9];
        const float* rtA = &sT[cs][tid * 9];
        const float* rtB = &sT[cs][(tid + NTHREADS) * 9];

        f2 p[9], tv[9];
        #pragma unroll
        for (int k = 0; k < 9; k++) {
            float pa = rpA[k], pb2 = rpB[k];
            float ta = rtA[k], tb2 = rtB[k];
            f2 traw = f2pack(ta, tb2);
            p[k]  = f2pack(clip10(pa), clip10(pb2));
            tv[k] = f2pack(clip10(ta), clip10(tb2));
            l2a = f2fma(p[k], p[k], l2a);
            f2 d = f2fma(traw, KNEG1, p[k]);   // clip(p) - raw t
            fba = f2fma(d, d, fba);
        }

        // ortho (clipped pred columns); off-diag factor 2 applied at the end
        {
            f2 c11 = f2fma(p[0], p[0], f2fma(p[3], p[3], f2mul(p[6], p[6])));
            f2 c22 = f2fma(p[1], p[1], f2fma(p[4], p[4], f2mul(p[7], p[7])));
            f2 c33 = f2fma(p[2], p[2], f2fma(p[5], p[5], f2mul(p[8], p[8])));
            f2 c12 = f2fma(p[0], p[1], f2fma(p[3], p[4], f2mul(p[6], p[7])));
            f2 c13 = f2fma(p[0], p[2], f2fma(p[3], p[5], f2mul(p[6], p[8])));
            f2 c23 = f2fma(p[1], p[2], f2fma(p[4], p[5], f2mul(p[7], p[8])));
            f2 d11 = f2add(c11, KNEG1);
            f2 d22 = f2add(c22, KNEG1);
            f2 d33 = f2add(c33, KNEG1);
            orda = f2fma(d11, d11, f2fma(d22, d22, f2fma(d33, d33, orda)));
            oroa = f2fma(c12, c12, f2fma(c13, c13, f2fma(c23, c23, oroa)));
        }

        f2 eP[9], eT[9];
        gs3x3_p(p, eP);
        gs3x3_p(tv, eT);

        f2 tr = f2mul(eP[0], eT[0]);
        #pragma unroll
        for (int k = 1; k < 9; k++) tr = f2fma(eP[k], eT[k], tr);
        tra = f2add(tra, tr);                  // chordal = 6 - 2*tr, folded later

        float trl, trh; f2unpack(tr, trl, trh);
        ang += angle_from_trace(trl) + angle_from_trace(trh);

        __syncthreads();  // all threads done reading stage cs

        int nt = t + STAGES * grid;
        if (tid == 0 && nt < NT) {
            mbar_expect_tx(mb[cs], 2 * TILE_BYTES);
            bulk_g2s(pb[cs], pred + (long long)nt * TILE_F, TILE_BYTES, mb[cs]);
            bulk_g2s(tb[cs], tgt  + (long long)nt * TILE_F, TILE_BYTES, mb[cs]);
        }
        if (++cs == STAGES) { cs = 0; cph ^= 1; }
    }

    // Remainder rows (B not multiple of TILE): block 0, scalar path.
    if (blockIdx.x == 0) {
        for (int r = NT * TILE + tid; r < B; r += NTHREADS, cnt++) {
            float pv[9], tvs[9];
            #pragma unroll
            for (int k = 0; k < 9; k++) {
                float praw = pred[(long long)r * 9 + k];
                float traw = tgt [(long long)r * 9 + k];
                float pcl = clip10(praw);
                pv[k] = pcl; tvs[k] = clip10(traw);
                l2_s = fmaf(pcl, pcl, l2_s);
                float d = pcl - traw;
                fb_s = fmaf(d, d, fb_s);
            }
            float c11 = fmaf(pv[0], pv[0], fmaf(pv[3], pv[3], pv[6] * pv[6]));
            float c22 = fmaf(pv[1], pv[1], fmaf(pv[4], pv[4], pv[7] * pv[7]));
            float c33 = fmaf(pv[2], pv[2], fmaf(pv[5], pv[5], pv[8] * pv[8]));
            float c12 = fmaf(pv[0], pv[1], fmaf(pv[3], pv[4], pv[6] * pv[7]));
            float c13 = fmaf(pv[0], pv[2], fmaf(pv[3], pv[5], pv[6] * pv[8]));
            float c23 = fmaf(pv[1], pv[2], fmaf(pv[4], pv[5], pv[7] * pv[8]));
            float d11 = c11 - 1.0f, d22 = c22 - 1.0f, d33 = c33 - 1.0f;
            or_s += d11 * d11 + d22 * d22 + d33 * d33
                  + 2.0f * (c12 * c12 + c13 * c13 + c23 * c23);
            float eP[9], eT[9];
            gs3x3_s(pv, eP);
            gs3x3_s(tvs, eT);
            float tr = 0.0f;
            #pragma unroll
            for (int k = 0; k < 9; k++) tr = fmaf(eP[k], eT[k], tr);
            tr_s += tr;
            ang += angle_from_trace(tr);
        }
    }

    // ---- fold packed accumulators to scalars ----
    float v0, v1, v2, v3, v4;
    {
        float lo, hi;
        f2unpack(tra, lo, hi);
        float trsum = lo + hi + tr_s;
        v0 = 6.0f * (float)cnt - 2.0f * trsum;       // chordal
        v1 = ang;                                     // angular
        f2unpack(orda, lo, hi); float od = lo + hi;
        f2unpack(oroa, lo, hi); float oo = lo + hi;
        v2 = od + 2.0f * oo + or_s;                   // ortho
        f2unpack(l2a, lo, hi);  v3 = lo + hi + l2_s;  // l2
        f2unpack(fba, lo, hi);  v4 = lo + hi + fb_s;  // fallback
    }

    // ---- block reduction (4 warps) ----
    #pragma unroll
    for (int off = 16; off > 0; off >>= 1) {
        v0 += __shfl_down_sync(0xFFFFFFFFu, v0, off);
        v1 += __shfl_down_sync(0xFFFFFFFFu, v1, off);
        v2 += __shfl_down_sync(0xFFFFFFFFu, v2, off);
        v3 += __shfl_down_sync(0xFFFFFFFFu, v3, off);
        v4 += __shfl_down_sync(0xFFFFFFFFu, v4, off);
    }
    const int wid = tid >> 5;
    const int lid = tid & 31;
    if (lid == 0) {
        red[wid][0] = v0; red[wid][1] = v1; red[wid][2] = v2;
        red[wid][3] = v3; red[wid][4] = v4;
    }
    __syncthreads();
    if (tid == 0) {
        float s0 = 0, s1 = 0, s2 = 0, s3 = 0, s4 = 0;
        #pragma unroll
        for (int w = 0; w < 4; w++) {
            s0 += red[w][0]; s1 += red[w][1]; s2 += red[w][2];
            s3 += red[w][3]; s4 += red[w][4];
        }
        float* slot = &g_part[blockIdx.x * 5];
        slot[0] = s0; slot[1] = s1; slot[2] = s2; slot[3] = s3; slot[4] = s4;
        __threadfence();
        unsigned int n = atomicAdd(&g_count, 1u);
        s_islast = (n == (unsigned int)(grid - 1)) ? 1 : 0;
    }
    __syncthreads();

    // ---- last block: final reduce + output ----
    if (s_islast) {
        double a0 = 0, a1 = 0, a2 = 0, a3 = 0, a4 = 0;
        for (int i = tid; i < grid; i += NTHREADS) {
            const float* slot = &g_part[i * 5];
            a0 += (double)__ldcg(&slot[0]);
            a1 += (double)__ldcg(&slot[1]);
            a2 += (double)__ldcg(&slot[2]);
            a3 += (double)__ldcg(&slot[3]);
            a4 += (double)__ldcg(&slot[4]);
        }
        #pragma unroll
        for (int off = 16; off > 0; off >>= 1) {
            a0 += __shfl_down_sync(0xFFFFFFFFu, a0, off);
            a1 += __shfl_down_sync(0xFFFFFFFFu, a1, off);
            a2 += __shfl_down_sync(0xFFFFFFFFu, a2, off);
            a3 += __shfl_down_sync(0xFFFFFFFFu, a3, off);
            a4 += __shfl_down_sync(0xFFFFFFFFu, a4, off);
        }
        __shared__ double dred[4][5];
        if (lid == 0) {
            dred[wid][0] = a0; dred[wid][1] = a1; dred[wid][2] = a2;
            dred[wid][3] = a3; dred[wid][4] = a4;
        }
        __syncthreads();
        if (tid == 0) {
            double s0 = 0, s1 = 0, s2 = 0, s3 = 0, s4 = 0;
            #pragma unroll
            for (int w = 0; w < 4; w++) {
                s0 += dred[w][0]; s1 += dred[w][1]; s2 += dred[w][2];
                s3 += dred[w][3]; s4 += dred[w][4];
            }
            double chordal  = s0 * invB;
            double angular  = s1 * invB;
            double ortho    = s2 * invB;
            double l2v      = s3 * invB9;
            double fallback = s4 * invB9;
            double total = chordal + 0.1 * angular + 0.01 * ortho + 1e-4 * l2v;
            float tf = (float)total;
            out[0] = (tf != tf) ? (float)fallback : tf;
            g_count = 0;   // reset for next graph replay
        }
    }
}

extern "C" void kernel_launch(void* const* d_in, const int* in_sizes, int n_in,
                              void* d_out, int out_size) {
    const float* pred = (const float*)d_in[0];
    const float* tgt  = (const float*)d_in[1];
    float* out = (float*)d_out;

    const int n = in_sizes[0];
    const int B = n / 9;
    const int NT = B / TILE;

    int nsm = 148, bpm = 4;
    cudaDeviceGetAttribute(&nsm, cudaDevAttrMultiProcessorCount, 0);
    cudaOccupancyMaxActiveBlocksPerMultiprocessor(&bpm, rot_loss_pipe, NTHREADS, 0);
    if (bpm < 1) bpm = 1;
    int grid = nsm * bpm;
    if (grid > NT && NT > 0) grid = NT;
    if (grid < 1) grid = 1;
    if (grid > MAXGRID) grid = MAXGRID;

    rot_loss_pipe<<<grid, NTHREADS>>>(pred, tgt, NT, B, grid,
                                      1.0 / (double)B, 1.0 / ((double)B * 9.0), out);
}